// round 4
// baseline (speedup 1.0000x reference)
#include <cuda_runtime.h>

// Depthwise 1D conv: B=8, F=64, L=131072, K=9, pad=4 (SAME).
// x:      (B, F, L) float32, row (b,f) at (b*F + f)*L
// kernel: (F, 1, 9) float32
// out:    (F, B, 1, L) float32, row (f,b) at (f*B + b)*L
//
// One thread -> one float4 of outputs. Inputs needed: x[p-4 .. p+7] = 3 aligned
// float4 loads (zero-filled at row boundaries). Weights are warp-uniform loads.

#define Lc 131072
#define Fc 64
#define Bc 8
#define QUADS_PER_ROW (Lc / 4)            // 32768 = 2^15

__global__ __launch_bounds__(256) void dwconv1d_kernel(
    const float* __restrict__ x,
    const float* __restrict__ w,
    float* __restrict__ out)
{
    int t = blockIdx.x * blockDim.x + threadIdx.x;
    int q   = t & (QUADS_PER_ROW - 1);    // quad index within row
    int row = t >> 15;                    // b*F + f
    int f = row & (Fc - 1);
    int b = row >> 6;
    int p = q << 2;                       // element offset within row

    const float* xr = x + (size_t)row * Lc;

    // 9 warp-uniform weight loads (all threads in a block share f)
    const float* wf = w + f * 9;
    float k0 = wf[0], k1 = wf[1], k2 = wf[2], k3 = wf[3], k4 = wf[4],
          k5 = wf[5], k6 = wf[6], k7 = wf[7], k8 = wf[8];

    float4 x0 = *reinterpret_cast<const float4*>(xr + p);
    float4 xm = make_float4(0.f, 0.f, 0.f, 0.f);
    float4 xp = make_float4(0.f, 0.f, 0.f, 0.f);
    if (p >= 4)      xm = *reinterpret_cast<const float4*>(xr + p - 4);
    if (p + 4 < Lc)  xp = *reinterpret_cast<const float4*>(xr + p + 4);

    // a[i] = x[p - 4 + i], i = 0..11
    float a0 = xm.x, a1 = xm.y, a2  = xm.z, a3  = xm.w;
    float a4 = x0.x, a5 = x0.y, a6  = x0.z, a7  = x0.w;
    float a8 = xp.x, a9 = xp.y, a10 = xp.z, a11 = xp.w;

    float4 o;
    // out[p+j] = sum_k x[p+j-4+k] * w[k]  ->  sum_k a[j+k] * w[k]
    o.x = a0*k0 + a1*k1 + a2*k2 + a3*k3 + a4*k4 + a5*k5 + a6*k6 + a7*k7 + a8*k8;
    o.y = a1*k0 + a2*k1 + a3*k2 + a4*k3 + a5*k4 + a6*k5 + a7*k6 + a8*k7 + a9*k8;
    o.z = a2*k0 + a3*k1 + a4*k2 + a5*k3 + a6*k4 + a7*k5 + a8*k6 + a9*k7 + a10*k8;
    o.w = a3*k0 + a4*k1 + a5*k2 + a6*k3 + a7*k4 + a8*k5 + a9*k6 + a10*k7 + a11*k8;

    *reinterpret_cast<float4*>(out + ((size_t)(f * Bc + b)) * Lc + p) = o;
}

extern "C" void kernel_launch(void* const* d_in, const int* in_sizes, int n_in,
                              void* d_out, int out_size)
{
    const float* x = (const float*)d_in[0];
    const float* w = (const float*)d_in[1];
    float* out = (float*)d_out;

    // total quads = B*F*L/4 = 16,777,216 ; 256 threads/block -> 65536 blocks
    dim3 grid((Bc * Fc * QUADS_PER_ROW) / 256);
    dwconv1d_kernel<<<grid, 256>>>(x, w, out);
}